// round 1
// baseline (speedup 1.0000x reference)
#include <cuda_runtime.h>
#include <math.h>

// ---- problem constants ----
#define NL 12
#define NH 12
#define NC 768
#define NV 50257
#define NT 1024
#define NB 4
#define ND 64
#define NTOK (NB * NT)   // 4096

// ---- scratch (device globals; no allocation allowed) ----
__device__ float g_x[NTOK * NC];        // residual stream
__device__ float g_h[NTOK * NC];        // layernorm output
__device__ float g_qkv[NTOK * 3 * NC];  // qkv projections
__device__ float g_y[NTOK * NC];        // attention output
__device__ float g_fc[NTOK * 4 * NC];   // mlp hidden

// =====================================================================
// Embedding: x[b,t,:] = wte[idx[b,t],:] + wpe[t,:]
// =====================================================================
__global__ void embed_kernel(const int* __restrict__ idx,
                             const float* __restrict__ wte,
                             const float* __restrict__ wpe,
                             float* __restrict__ x) {
    int row = blockIdx.x;            // 0..NTOK-1
    int t = row % NT;
    int tok = idx[row];
    const float* we = wte + (size_t)tok * NC;
    const float* wp = wpe + (size_t)t * NC;
    float* out = x + (size_t)row * NC;
    for (int c = threadIdx.x; c < NC; c += blockDim.x)
        out[c] = we[c] + wp[c];
}

// =====================================================================
// LayerNorm: one block per row of 768
// =====================================================================
__global__ void ln_kernel(const float* __restrict__ x,
                          const float* __restrict__ w,
                          const float* __restrict__ b,
                          float* __restrict__ out) {
    int row = blockIdx.x;
    const float* xr = x + (size_t)row * NC;
    __shared__ float red[32];
    int tid = threadIdx.x;
    int nwarp = blockDim.x >> 5;

    // mean
    float s = 0.f;
    for (int c = tid; c < NC; c += blockDim.x) s += xr[c];
    #pragma unroll
    for (int o = 16; o; o >>= 1) s += __shfl_xor_sync(0xffffffffu, s, o);
    if ((tid & 31) == 0) red[tid >> 5] = s;
    __syncthreads();
    if (tid < 32) {
        float v = (tid < nwarp) ? red[tid] : 0.f;
        #pragma unroll
        for (int o = 16; o; o >>= 1) v += __shfl_xor_sync(0xffffffffu, v, o);
        if (tid == 0) red[0] = v;
    }
    __syncthreads();
    float mu = red[0] * (1.0f / NC);
    __syncthreads();

    // variance
    float s2 = 0.f;
    for (int c = tid; c < NC; c += blockDim.x) {
        float d = xr[c] - mu;
        s2 += d * d;
    }
    #pragma unroll
    for (int o = 16; o; o >>= 1) s2 += __shfl_xor_sync(0xffffffffu, s2, o);
    if ((tid & 31) == 0) red[tid >> 5] = s2;
    __syncthreads();
    if (tid < 32) {
        float v = (tid < nwarp) ? red[tid] : 0.f;
        #pragma unroll
        for (int o = 16; o; o >>= 1) v += __shfl_xor_sync(0xffffffffu, v, o);
        if (tid == 0) red[0] = v;
    }
    __syncthreads();
    float var = red[0] * (1.0f / NC);
    float rstd = rsqrtf(var + 1e-5f);
    float* outr = out + (size_t)row * NC;
    for (int c = tid; c < NC; c += blockDim.x)
        outr[c] = (xr[c] - mu) * rstd * w[c] + b[c];
}

// =====================================================================
// SGEMM (NN): C[M,N] = A[M,K] @ W[K,N] (+bias) (opt gelu) (+res)
// BM=BN=64, BK=16, 256 threads, 4x4 per thread.
// M must be a multiple of 64, K a multiple of 16. N may be ragged.
// =====================================================================
#define BM 64
#define BN 64
#define BK 16

__device__ __forceinline__ float gelu_f(float u) {
    return 0.5f * u * (1.0f + tanhf(0.7978845608028654f * (u + 0.044715f * u * u * u)));
}

__global__ void sgemm_nn(const float* __restrict__ A, const float* __restrict__ W,
                         const float* __restrict__ bias, const float* __restrict__ res,
                         float* __restrict__ C, int M, int N, int K, int act) {
    __shared__ float As[BK][BM];
    __shared__ float Bs[BK][BN];
    int tid = threadIdx.x;
    int tx = tid & 15, ty = tid >> 4;
    int bm = blockIdx.y * BM, bn = blockIdx.x * BN;
    bool nfull = (bn + BN <= N);
    float acc[4][4] = {};

    for (int k0 = 0; k0 < K; k0 += BK) {
        { // A tile: 64x16, float4 per thread
            int r = tid >> 2, c4 = (tid & 3) << 2;
            const float4 a = *(const float4*)(A + (size_t)(bm + r) * K + k0 + c4);
            As[c4 + 0][r] = a.x; As[c4 + 1][r] = a.y;
            As[c4 + 2][r] = a.z; As[c4 + 3][r] = a.w;
        }
        { // B tile: 16x64
            int r = tid >> 4, c4 = (tid & 15) << 2;
            if (nfull) {
                const float4 bv = *(const float4*)(W + (size_t)(k0 + r) * N + bn + c4);
                Bs[r][c4 + 0] = bv.x; Bs[r][c4 + 1] = bv.y;
                Bs[r][c4 + 2] = bv.z; Bs[r][c4 + 3] = bv.w;
            } else {
                #pragma unroll
                for (int i = 0; i < 4; i++) {
                    int n = bn + c4 + i;
                    Bs[r][c4 + i] = (n < N) ? W[(size_t)(k0 + r) * N + n] : 0.f;
                }
            }
        }
        __syncthreads();
        #pragma unroll
        for (int kk = 0; kk < BK; kk++) {
            float av[4], bv[4];
            #pragma unroll
            for (int i = 0; i < 4; i++) av[i] = As[kk][ty * 4 + i];
            #pragma unroll
            for (int j = 0; j < 4; j++) bv[j] = Bs[kk][tx * 4 + j];
            #pragma unroll
            for (int i = 0; i < 4; i++)
                #pragma unroll
                for (int j = 0; j < 4; j++)
                    acc[i][j] = fmaf(av[i], bv[j], acc[i][j]);
        }
        __syncthreads();
    }

    #pragma unroll
    for (int i = 0; i < 4; i++) {
        int m = bm + ty * 4 + i;
        #pragma unroll
        for (int j = 0; j < 4; j++) {
            int n = bn + tx * 4 + j;
            if (n < N) {
                float v = acc[i][j];
                if (bias) v += bias[n];
                if (act) v = gelu_f(v);
                if (res) v += res[(size_t)m * N + n];
                C[(size_t)m * N + n] = v;
            }
        }
    }
}

// =====================================================================
// SGEMM (NT): C[M,N] = A[M,K] @ Bt[N,K]^T  (lm_head). No bias.
// =====================================================================
__global__ void sgemm_nt(const float* __restrict__ A, const float* __restrict__ Bt,
                         float* __restrict__ C, int M, int N, int K) {
    __shared__ float As[BK][BM];
    __shared__ float Bs[BK][BN];
    int tid = threadIdx.x;
    int tx = tid & 15, ty = tid >> 4;
    int bm = blockIdx.y * BM, bn = blockIdx.x * BN;
    float acc[4][4] = {};

    for (int k0 = 0; k0 < K; k0 += BK) {
        { // A tile
            int r = tid >> 2, c4 = (tid & 3) << 2;
            const float4 a = *(const float4*)(A + (size_t)(bm + r) * K + k0 + c4);
            As[c4 + 0][r] = a.x; As[c4 + 1][r] = a.y;
            As[c4 + 2][r] = a.z; As[c4 + 3][r] = a.w;
        }
        { // B tile from Bt[N,K]: n = tid/4, k-quad = tid%4
            int n = tid >> 2, c4 = (tid & 3) << 2;
            int gn = bn + n;
            if (gn < N) {
                const float4 bv = *(const float4*)(Bt + (size_t)gn * K + k0 + c4);
                Bs[c4 + 0][n] = bv.x; Bs[c4 + 1][n] = bv.y;
                Bs[c4 + 2][n] = bv.z; Bs[c4 + 3][n] = bv.w;
            } else {
                Bs[c4 + 0][n] = 0.f; Bs[c4 + 1][n] = 0.f;
                Bs[c4 + 2][n] = 0.f; Bs[c4 + 3][n] = 0.f;
            }
        }
        __syncthreads();
        #pragma unroll
        for (int kk = 0; kk < BK; kk++) {
            float av[4], bv[4];
            #pragma unroll
            for (int i = 0; i < 4; i++) av[i] = As[kk][ty * 4 + i];
            #pragma unroll
            for (int j = 0; j < 4; j++) bv[j] = Bs[kk][tx * 4 + j];
            #pragma unroll
            for (int i = 0; i < 4; i++)
                #pragma unroll
                for (int j = 0; j < 4; j++)
                    acc[i][j] = fmaf(av[i], bv[j], acc[i][j]);
        }
        __syncthreads();
    }

    #pragma unroll
    for (int i = 0; i < 4; i++) {
        int m = bm + ty * 4 + i;
        #pragma unroll
        for (int j = 0; j < 4; j++) {
            int n = bn + tx * 4 + j;
            if (n < N)
                C[(size_t)m * N + n] = acc[i][j];
        }
    }
}

// =====================================================================
// Causal attention, one block per (q, head, batch). 128 threads.
// qkv layout: [NTOK, 3*NC]; q at col h*64, k at NC + h*64, v at 2*NC + h*64
// =====================================================================
__global__ void attn_kernel(const float* __restrict__ qkv, float* __restrict__ y) {
    int q = blockIdx.x;
    int h = blockIdx.y;
    int b = blockIdx.z;
    int tid = threadIdx.x;

    __shared__ float qs[ND];
    __shared__ float sc[NT];
    __shared__ float red[32];
    __shared__ float yp[2][ND];

    const size_t rs = 3 * NC;
    const float* qptr = qkv + ((size_t)(b * NT + q)) * rs + h * ND;
    if (tid < ND) qs[tid] = qptr[tid];
    __syncthreads();

    const float scale = 0.125f;  // 1/sqrt(64)
    int nk = q + 1;
    const float* kbase = qkv + ((size_t)b * NT) * rs + NC + h * ND;
    for (int k = tid; k < nk; k += blockDim.x) {
        const float* kp = kbase + (size_t)k * rs;
        float d = 0.f;
        #pragma unroll
        for (int i = 0; i < ND; i++) d = fmaf(qs[i], kp[i], d);
        sc[k] = d * scale;
    }
    __syncthreads();

    // max
    float m = -1e30f;
    for (int k = tid; k < nk; k += blockDim.x) m = fmaxf(m, sc[k]);
    #pragma unroll
    for (int o = 16; o; o >>= 1) m = fmaxf(m, __shfl_xor_sync(0xffffffffu, m, o));
    if ((tid & 31) == 0) red[tid >> 5] = m;
    __syncthreads();
    if (tid < 32) {
        float v = (tid < (int)(blockDim.x >> 5)) ? red[tid] : -1e30f;
        #pragma unroll
        for (int o = 16; o; o >>= 1) v = fmaxf(v, __shfl_xor_sync(0xffffffffu, v, o));
        if (tid == 0) red[0] = v;
    }
    __syncthreads();
    m = red[0];
    __syncthreads();

    // exp + sum
    float s = 0.f;
    for (int k = tid; k < nk; k += blockDim.x) {
        float e = __expf(sc[k] - m);
        sc[k] = e;
        s += e;
    }
    #pragma unroll
    for (int o = 16; o; o >>= 1) s += __shfl_xor_sync(0xffffffffu, s, o);
    if ((tid & 31) == 0) red[tid >> 5] = s;
    __syncthreads();
    if (tid < 32) {
        float v = (tid < (int)(blockDim.x >> 5)) ? red[tid] : 0.f;
        #pragma unroll
        for (int o = 16; o; o >>= 1) v += __shfl_xor_sync(0xffffffffu, v, o);
        if (tid == 0) red[0] = v;
    }
    __syncthreads();
    float inv = 1.0f / red[0];

    // y[d] = inv * sum_k p[k] * v[k,d]; 2 partitions x 64 dims
    int part = tid >> 6, d = tid & 63;
    const float* vbase = qkv + ((size_t)b * NT) * rs + 2 * NC + h * ND;
    float acc = 0.f;
    for (int k = part; k < nk; k += 2)
        acc = fmaf(sc[k], vbase[(size_t)k * rs + d], acc);
    yp[part][d] = acc;
    __syncthreads();
    if (tid < ND)
        y[((size_t)(b * NT + q)) * NC + h * ND + tid] = (yp[0][tid] + yp[1][tid]) * inv;
}

// =====================================================================
// launch
// =====================================================================
extern "C" void kernel_launch(void* const* d_in, const int* in_sizes, int n_in,
                              void* d_out, int out_size) {
    const int*   idx    = (const int*)d_in[0];
    const float* wte    = (const float*)d_in[1];
    const float* wpe    = (const float*)d_in[2];
    const float* ln1_w  = (const float*)d_in[3];
    const float* ln1_b  = (const float*)d_in[4];
    const float* ln2_w  = (const float*)d_in[5];
    const float* ln2_b  = (const float*)d_in[6];
    const float* attn_w = (const float*)d_in[7];
    const float* attn_b = (const float*)d_in[8];
    const float* proj_w = (const float*)d_in[9];
    const float* proj_b = (const float*)d_in[10];
    const float* fc_w   = (const float*)d_in[11];
    const float* fc_b   = (const float*)d_in[12];
    const float* fcp_w  = (const float*)d_in[13];
    const float* fcp_b  = (const float*)d_in[14];
    const float* lnf_w  = (const float*)d_in[15];
    const float* lnf_b  = (const float*)d_in[16];
    const float* lmh    = (const float*)d_in[17];
    float* out = (float*)d_out;

    float *x, *h, *qkv, *y, *fc;
    cudaGetSymbolAddress((void**)&x, g_x);
    cudaGetSymbolAddress((void**)&h, g_h);
    cudaGetSymbolAddress((void**)&qkv, g_qkv);
    cudaGetSymbolAddress((void**)&y, g_y);
    cudaGetSymbolAddress((void**)&fc, g_fc);

    embed_kernel<<<NTOK, 256>>>(idx, wte, wpe, x);

    for (int l = 0; l < NL; l++) {
        // ln1
        ln_kernel<<<NTOK, 256>>>(x, ln1_w + l * NC, ln1_b + l * NC, h);
        // qkv = h @ attn_w[l] + attn_b[l]
        {
            dim3 grid((3 * NC) / BN, NTOK / BM);
            sgemm_nn<<<grid, 256>>>(h, attn_w + (size_t)l * NC * 3 * NC,
                                    attn_b + (size_t)l * 3 * NC, nullptr,
                                    qkv, NTOK, 3 * NC, NC, 0);
        }
        // attention
        {
            dim3 grid(NT, NH, NB);
            attn_kernel<<<grid, 128>>>(qkv, y);
        }
        // x = x + y @ proj_w + proj_b
        {
            dim3 grid(NC / BN, NTOK / BM);
            sgemm_nn<<<grid, 256>>>(y, proj_w + (size_t)l * NC * NC,
                                    proj_b + (size_t)l * NC, x,
                                    x, NTOK, NC, NC, 0);
        }
        // ln2
        ln_kernel<<<NTOK, 256>>>(x, ln2_w + l * NC, ln2_b + l * NC, h);
        // fc = gelu(h @ fc_w + fc_b)
        {
            dim3 grid((4 * NC) / BN, NTOK / BM);
            sgemm_nn<<<grid, 256>>>(h, fc_w + (size_t)l * NC * 4 * NC,
                                    fc_b + (size_t)l * 4 * NC, nullptr,
                                    fc, NTOK, 4 * NC, NC, 1);
        }
        // x = x + fc @ fcp_w + fcp_b
        {
            dim3 grid(NC / BN, NTOK / BM);
            sgemm_nn<<<grid, 256>>>(fc, fcp_w + (size_t)l * 4 * NC * NC,
                                    fcp_b + (size_t)l * NC, x,
                                    x, NTOK, NC, 4 * NC, 0);
        }
    }

    // final layernorm
    ln_kernel<<<NTOK, 256>>>(x, lnf_w, lnf_b, h);

    // logits = h @ lm_head^T
    {
        dim3 grid((NV + BN - 1) / BN, NTOK / BM);
        sgemm_nt<<<grid, 256>>>(h, lmh, out, NTOK, NV, NC);
    }
}

// round 2
// speedup vs baseline: 1.1301x; 1.1301x over previous
#include <cuda_runtime.h>
#include <math.h>

// ---- problem constants ----
#define NL 12
#define NH 12
#define NC 768
#define NV 50257
#define NT 1024
#define NB 4
#define ND 64
#define NTOK (NB * NT)   // 4096

// ---- scratch (device globals; no allocation allowed) ----
__device__ float g_x[NTOK * NC];        // residual stream
__device__ float g_h[NTOK * NC];        // layernorm output
__device__ float g_qkv[NTOK * 3 * NC];  // qkv projections
__device__ float g_y[NTOK * NC];        // attention output
__device__ float g_fc[NTOK * 4 * NC];   // mlp hidden

// =====================================================================
// Embedding
// =====================================================================
__global__ void embed_kernel(const int* __restrict__ idx,
                             const float* __restrict__ wte,
                             const float* __restrict__ wpe,
                             float* __restrict__ x) {
    int row = blockIdx.x;
    int t = row % NT;
    int tok = idx[row];
    const float* we = wte + (size_t)tok * NC;
    const float* wp = wpe + (size_t)t * NC;
    float* out = x + (size_t)row * NC;
    for (int c = threadIdx.x; c < NC; c += blockDim.x)
        out[c] = we[c] + wp[c];
}

// =====================================================================
// LayerNorm: one block per row of 768
// =====================================================================
__global__ void ln_kernel(const float* __restrict__ x,
                          const float* __restrict__ w,
                          const float* __restrict__ b,
                          float* __restrict__ out) {
    int row = blockIdx.x;
    const float* xr = x + (size_t)row * NC;
    __shared__ float red[32];
    int tid = threadIdx.x;
    int nwarp = blockDim.x >> 5;

    float s = 0.f;
    for (int c = tid; c < NC; c += blockDim.x) s += xr[c];
    #pragma unroll
    for (int o = 16; o; o >>= 1) s += __shfl_xor_sync(0xffffffffu, s, o);
    if ((tid & 31) == 0) red[tid >> 5] = s;
    __syncthreads();
    if (tid < 32) {
        float v = (tid < nwarp) ? red[tid] : 0.f;
        #pragma unroll
        for (int o = 16; o; o >>= 1) v += __shfl_xor_sync(0xffffffffu, v, o);
        if (tid == 0) red[0] = v;
    }
    __syncthreads();
    float mu = red[0] * (1.0f / NC);
    __syncthreads();

    float s2 = 0.f;
    for (int c = tid; c < NC; c += blockDim.x) {
        float d = xr[c] - mu;
        s2 += d * d;
    }
    #pragma unroll
    for (int o = 16; o; o >>= 1) s2 += __shfl_xor_sync(0xffffffffu, s2, o);
    if ((tid & 31) == 0) red[tid >> 5] = s2;
    __syncthreads();
    if (tid < 32) {
        float v = (tid < nwarp) ? red[tid] : 0.f;
        #pragma unroll
        for (int o = 16; o; o >>= 1) v += __shfl_xor_sync(0xffffffffu, v, o);
        if (tid == 0) red[0] = v;
    }
    __syncthreads();
    float var = red[0] * (1.0f / NC);
    float rstd = rsqrtf(var + 1e-5f);
    float* outr = out + (size_t)row * NC;
    for (int c = tid; c < NC; c += blockDim.x)
        outr[c] = (xr[c] - mu) * rstd * w[c] + b[c];
}

// =====================================================================
// Tensor-core GEMM: tf32 3x-split mma.sync, block 128x64x32, 8 warps
// =====================================================================
#define TBM 128
#define TBN 64
#define TBK 32

__device__ __forceinline__ float gelu_f(float u) {
    return 0.5f * u * (1.0f + tanhf(0.7978845608028654f * (u + 0.044715f * u * u * u)));
}

__device__ __forceinline__ void split_tf32(float x, unsigned& hi, unsigned& lo) {
    unsigned h;
    asm("cvt.rna.tf32.f32 %0, %1;" : "=r"(h) : "f"(x));
    float l = x - __uint_as_float(h);
    asm("cvt.rna.tf32.f32 %0, %1;" : "=r"(lo) : "f"(l));
    hi = h;
}

__device__ __forceinline__ void mma_tf32(float* c,
                                         unsigned a0, unsigned a1, unsigned a2, unsigned a3,
                                         unsigned b0, unsigned b1) {
    asm volatile(
        "mma.sync.aligned.m16n8k8.row.col.f32.tf32.tf32.f32 "
        "{%0,%1,%2,%3}, {%4,%5,%6,%7}, {%8,%9}, {%0,%1,%2,%3};"
        : "+f"(c[0]), "+f"(c[1]), "+f"(c[2]), "+f"(c[3])
        : "r"(a0), "r"(a1), "r"(a2), "r"(a3), "r"(b0), "r"(b1));
}

// NN: C[M,N] = A[M,K] @ W[K,N] (+bias)(gelu?)(+res). N % 64 == 0, K % 32 == 0, M % 128 == 0.
__global__ void __launch_bounds__(256) tc_gemm_nn(
    const float* __restrict__ A, const float* __restrict__ W,
    const float* __restrict__ bias, const float* __restrict__ res,
    float* __restrict__ C, int M, int N, int K, int act)
{
    __shared__ float As[TBM][TBK + 4];
    __shared__ float Bs[TBK][TBN + 8];

    int tid = threadIdx.x;
    int lane = tid & 31, warp = tid >> 5;
    int wm = (warp & 3) * 32;
    int wn = (warp >> 2) * 32;
    int g = lane >> 2, t4 = lane & 3;

    int bm = blockIdx.y * TBM;
    int bn = blockIdx.x * TBN;

    float c[2][4][4] = {};

    for (int k0 = 0; k0 < K; k0 += TBK) {
        #pragma unroll
        for (int i = 0; i < 4; i++) {
            int idx = tid + i * 256;
            int r = idx >> 3, c4 = (idx & 7) << 2;
            float4 v = *(const float4*)(A + (size_t)(bm + r) * K + k0 + c4);
            *(float4*)&As[r][c4] = v;
        }
        #pragma unroll
        for (int i = 0; i < 2; i++) {
            int idx = tid + i * 256;
            int r = idx >> 4, c4 = (idx & 15) << 2;
            float4 v = *(const float4*)(W + (size_t)(k0 + r) * N + bn + c4);
            *(float4*)&Bs[r][c4] = v;
        }
        __syncthreads();

        #pragma unroll
        for (int kk = 0; kk < TBK; kk += 8) {
            unsigned ah[2][4], al[2][4];
            #pragma unroll
            for (int im = 0; im < 2; im++) {
                int mo = wm + im * 16;
                split_tf32(As[mo + g][kk + t4],         ah[im][0], al[im][0]);
                split_tf32(As[mo + g + 8][kk + t4],     ah[im][1], al[im][1]);
                split_tf32(As[mo + g][kk + t4 + 4],     ah[im][2], al[im][2]);
                split_tf32(As[mo + g + 8][kk + t4 + 4], ah[im][3], al[im][3]);
            }
            #pragma unroll
            for (int jn = 0; jn < 4; jn++) {
                int no = wn + jn * 8 + g;
                unsigned bh0, bl0, bh1, bl1;
                split_tf32(Bs[kk + t4][no],     bh0, bl0);
                split_tf32(Bs[kk + t4 + 4][no], bh1, bl1);
                #pragma unroll
                for (int im = 0; im < 2; im++) {
                    mma_tf32(c[im][jn], ah[im][0], ah[im][1], ah[im][2], ah[im][3], bh0, bh1);
                    mma_tf32(c[im][jn], ah[im][0], ah[im][1], ah[im][2], ah[im][3], bl0, bl1);
                    mma_tf32(c[im][jn], al[im][0], al[im][1], al[im][2], al[im][3], bh0, bh1);
                }
            }
        }
        __syncthreads();
    }

    #pragma unroll
    for (int im = 0; im < 2; im++) {
        #pragma unroll
        for (int jn = 0; jn < 4; jn++) {
            int row0 = bm + wm + im * 16 + g;
            int col0 = bn + wn + jn * 8 + t4 * 2;
            #pragma unroll
            for (int p = 0; p < 4; p++) {
                int row = row0 + (p >> 1) * 8;
                int col = col0 + (p & 1);
                float v = c[im][jn][p];
                if (bias) v += bias[col];
                if (act) v = gelu_f(v);
                if (res) v += res[(size_t)row * N + col];
                C[(size_t)row * N + col] = v;
            }
        }
    }
}

// NT: C[M,N] = A[M,K] @ Bt[N,K]^T  (lm_head). Ragged N allowed. grid: (M/128, ceil(N/64))
__global__ void __launch_bounds__(256) tc_gemm_nt(
    const float* __restrict__ A, const float* __restrict__ Bt,
    float* __restrict__ C, int M, int N, int K)
{
    __shared__ float As[TBM][TBK + 4];
    __shared__ float Bs[TBK][TBN + 8];

    int tid = threadIdx.x;
    int lane = tid & 31, warp = tid >> 5;
    int wm = (warp & 3) * 32;
    int wn = (warp >> 2) * 32;
    int g = lane >> 2, t4 = lane & 3;

    int bm = blockIdx.x * TBM;   // m fastest -> B column tile shared in L2 across wave
    int bn = blockIdx.y * TBN;

    float c[2][4][4] = {};

    for (int k0 = 0; k0 < K; k0 += TBK) {
        #pragma unroll
        for (int i = 0; i < 4; i++) {
            int idx = tid + i * 256;
            int r = idx >> 3, c4 = (idx & 7) << 2;
            float4 v = *(const float4*)(A + (size_t)(bm + r) * K + k0 + c4);
            *(float4*)&As[r][c4] = v;
        }
        #pragma unroll
        for (int i = 0; i < 2; i++) {
            int idx = tid + i * 256;       // 0..511: n = idx%64, kq = (idx/64)*4
            int n = idx & 63;
            int kq = (idx >> 6) << 2;
            int gn = bn + n;
            float4 v = make_float4(0.f, 0.f, 0.f, 0.f);
            if (gn < N) v = *(const float4*)(Bt + (size_t)gn * K + k0 + kq);
            Bs[kq + 0][n] = v.x; Bs[kq + 1][n] = v.y;
            Bs[kq + 2][n] = v.z; Bs[kq + 3][n] = v.w;
        }
        __syncthreads();

        #pragma unroll
        for (int kk = 0; kk < TBK; kk += 8) {
            unsigned ah[2][4], al[2][4];
            #pragma unroll
            for (int im = 0; im < 2; im++) {
                int mo = wm + im * 16;
                split_tf32(As[mo + g][kk + t4],         ah[im][0], al[im][0]);
                split_tf32(As[mo + g + 8][kk + t4],     ah[im][1], al[im][1]);
                split_tf32(As[mo + g][kk + t4 + 4],     ah[im][2], al[im][2]);
                split_tf32(As[mo + g + 8][kk + t4 + 4], ah[im][3], al[im][3]);
            }
            #pragma unroll
            for (int jn = 0; jn < 4; jn++) {
                int no = wn + jn * 8 + g;
                unsigned bh0, bl0, bh1, bl1;
                split_tf32(Bs[kk + t4][no],     bh0, bl0);
                split_tf32(Bs[kk + t4 + 4][no], bh1, bl1);
                #pragma unroll
                for (int im = 0; im < 2; im++) {
                    mma_tf32(c[im][jn], ah[im][0], ah[im][1], ah[im][2], ah[im][3], bh0, bh1);
                    mma_tf32(c[im][jn], ah[im][0], ah[im][1], ah[im][2], ah[im][3], bl0, bl1);
                    mma_tf32(c[im][jn], al[im][0], al[im][1], al[im][2], al[im][3], bh0, bh1);
                }
            }
        }
        __syncthreads();
    }

    #pragma unroll
    for (int im = 0; im < 2; im++) {
        #pragma unroll
        for (int jn = 0; jn < 4; jn++) {
            int row0 = bm + wm + im * 16 + g;
            int col0 = bn + wn + jn * 8 + t4 * 2;
            #pragma unroll
            for (int p = 0; p < 4; p++) {
                int row = row0 + (p >> 1) * 8;
                int col = col0 + (p & 1);
                if (col < N)
                    C[(size_t)row * N + col] = c[im][jn][p];
            }
        }
    }
}

// =====================================================================
// Causal attention (unchanged; ~68us total)
// =====================================================================
__global__ void attn_kernel(const float* __restrict__ qkv, float* __restrict__ y) {
    int q = blockIdx.x;
    int h = blockIdx.y;
    int b = blockIdx.z;
    int tid = threadIdx.x;

    __shared__ float qs[ND];
    __shared__ float sc[NT];
    __shared__ float red[32];
    __shared__ float yp[2][ND];

    const size_t rs = 3 * NC;
    const float* qptr = qkv + ((size_t)(b * NT + q)) * rs + h * ND;
    if (tid < ND) qs[tid] = qptr[tid];
    __syncthreads();

    const float scale = 0.125f;
    int nk = q + 1;
    const float* kbase = qkv + ((size_t)b * NT) * rs + NC + h * ND;
    for (int k = tid; k < nk; k += blockDim.x) {
        const float* kp = kbase + (size_t)k * rs;
        float d = 0.f;
        #pragma unroll
        for (int i = 0; i < ND; i++) d = fmaf(qs[i], kp[i], d);
        sc[k] = d * scale;
    }
    __syncthreads();

    float m = -1e30f;
    for (int k = tid; k < nk; k += blockDim.x) m = fmaxf(m, sc[k]);
    #pragma unroll
    for (int o = 16; o; o >>= 1) m = fmaxf(m, __shfl_xor_sync(0xffffffffu, m, o));
    if ((tid & 31) == 0) red[tid >> 5] = m;
    __syncthreads();
    if (tid < 32) {
        float v = (tid < (int)(blockDim.x >> 5)) ? red[tid] : -1e30f;
        #pragma unroll
        for (int o = 16; o; o >>= 1) v = fmaxf(v, __shfl_xor_sync(0xffffffffu, v, o));
        if (tid == 0) red[0] = v;
    }
    __syncthreads();
    m = red[0];
    __syncthreads();

    float s = 0.f;
    for (int k = tid; k < nk; k += blockDim.x) {
        float e = __expf(sc[k] - m);
        sc[k] = e;
        s += e;
    }
    #pragma unroll
    for (int o = 16; o; o >>= 1) s += __shfl_xor_sync(0xffffffffu, s, o);
    if ((tid & 31) == 0) red[tid >> 5] = s;
    __syncthreads();
    if (tid < 32) {
        float v = (tid < (int)(blockDim.x >> 5)) ? red[tid] : 0.f;
        #pragma unroll
        for (int o = 16; o; o >>= 1) v += __shfl_xor_sync(0xffffffffu, v, o);
        if (tid == 0) red[0] = v;
    }
    __syncthreads();
    float inv = 1.0f / red[0];

    int part = tid >> 6, d = tid & 63;
    const float* vbase = qkv + ((size_t)b * NT) * rs + 2 * NC + h * ND;
    float acc = 0.f;
    for (int k = part; k < nk; k += 2)
        acc = fmaf(sc[k], vbase[(size_t)k * rs + d], acc);
    yp[part][d] = acc;
    __syncthreads();
    if (tid < ND)
        y[((size_t)(b * NT + q)) * NC + h * ND + tid] = (yp[0][tid] + yp[1][tid]) * inv;
}

// =====================================================================
// launch
// =====================================================================
extern "C" void kernel_launch(void* const* d_in, const int* in_sizes, int n_in,
                              void* d_out, int out_size) {
    const int*   idx    = (const int*)d_in[0];
    const float* wte    = (const float*)d_in[1];
    const float* wpe    = (const float*)d_in[2];
    const float* ln1_w  = (const float*)d_in[3];
    const float* ln1_b  = (const float*)d_in[4];
    const float* ln2_w  = (const float*)d_in[5];
    const float* ln2_b  = (const float*)d_in[6];
    const float* attn_w = (const float*)d_in[7];
    const float* attn_b = (const float*)d_in[8];
    const float* proj_w = (const float*)d_in[9];
    const float* proj_b = (const float*)d_in[10];
    const float* fc_w   = (const float*)d_in[11];
    const float* fc_b   = (const float*)d_in[12];
    const float* fcp_w  = (const float*)d_in[13];
    const float* fcp_b  = (const float*)d_in[14];
    const float* lnf_w  = (const float*)d_in[15];
    const float* lnf_b  = (const float*)d_in[16];
    const float* lmh    = (const float*)d_in[17];
    float* out = (float*)d_out;

    float *x, *h, *qkv, *y, *fc;
    cudaGetSymbolAddress((void**)&x, g_x);
    cudaGetSymbolAddress((void**)&h, g_h);
    cudaGetSymbolAddress((void**)&qkv, g_qkv);
    cudaGetSymbolAddress((void**)&y, g_y);
    cudaGetSymbolAddress((void**)&fc, g_fc);

    embed_kernel<<<NTOK, 256>>>(idx, wte, wpe, x);

    for (int l = 0; l < NL; l++) {
        ln_kernel<<<NTOK, 256>>>(x, ln1_w + l * NC, ln1_b + l * NC, h);
        {
            dim3 grid((3 * NC) / TBN, NTOK / TBM);
            tc_gemm_nn<<<grid, 256>>>(h, attn_w + (size_t)l * NC * 3 * NC,
                                      attn_b + (size_t)l * 3 * NC, nullptr,
                                      qkv, NTOK, 3 * NC, NC, 0);
        }
        {
            dim3 grid(NT, NH, NB);
            attn_kernel<<<grid, 128>>>(qkv, y);
        }
        {
            dim3 grid(NC / TBN, NTOK / TBM);
            tc_gemm_nn<<<grid, 256>>>(y, proj_w + (size_t)l * NC * NC,
                                      proj_b + (size_t)l * NC, x,
                                      x, NTOK, NC, NC, 0);
        }
        ln_kernel<<<NTOK, 256>>>(x, ln2_w + l * NC, ln2_b + l * NC, h);
        {
            dim3 grid((4 * NC) / TBN, NTOK / TBM);
            tc_gemm_nn<<<grid, 256>>>(h, fc_w + (size_t)l * NC * 4 * NC,
                                      fc_b + (size_t)l * 4 * NC, nullptr,
                                      fc, NTOK, 4 * NC, NC, 1);
        }
        {
            dim3 grid(NC / TBN, NTOK / TBM);
            tc_gemm_nn<<<grid, 256>>>(fc, fcp_w + (size_t)l * 4 * NC * NC,
                                      fcp_b + (size_t)l * NC, x,
                                      x, NTOK, NC, 4 * NC, 0);
        }
    }

    ln_kernel<<<NTOK, 256>>>(x, lnf_w, lnf_b, h);

    {
        dim3 grid(NTOK / TBM, (NV + TBN - 1) / TBN);
        tc_gemm_nt<<<grid, 256>>>(h, lmh, out, NTOK, NV, NC);
    }
}

// round 3
// speedup vs baseline: 1.1302x; 1.0001x over previous
#include <cuda_runtime.h>
#include <math.h>

// ---- problem constants ----
#define NL 12
#define NH 12
#define NC 768
#define NV 50257
#define NT 1024
#define NB 4
#define ND 64
#define NTOK (NB * NT)   // 4096

// ---- scratch (device globals; no allocation allowed) ----
__device__ float g_x[NTOK * NC];        // residual stream
__device__ float g_h[NTOK * NC];        // layernorm output
__device__ float g_qkv[NTOK * 3 * NC];  // qkv projections
__device__ float g_y[NTOK * NC];        // attention output
__device__ float g_fc[NTOK * 4 * NC];   // mlp hidden

// =====================================================================
// Embedding
// =====================================================================
__global__ void embed_kernel(const int* __restrict__ idx,
                             const float* __restrict__ wte,
                             const float* __restrict__ wpe,
                             float* __restrict__ x) {
    int row = blockIdx.x;
    int t = row % NT;
    int tok = idx[row];
    const float* we = wte + (size_t)tok * NC;
    const float* wp = wpe + (size_t)t * NC;
    float* out = x + (size_t)row * NC;
    for (int c = threadIdx.x; c < NC; c += blockDim.x)
        out[c] = we[c] + wp[c];
}

// =====================================================================
// LayerNorm: one block per row of 768
// =====================================================================
__global__ void ln_kernel(const float* __restrict__ x,
                          const float* __restrict__ w,
                          const float* __restrict__ b,
                          float* __restrict__ out) {
    int row = blockIdx.x;
    const float* xr = x + (size_t)row * NC;
    __shared__ float red[32];
    int tid = threadIdx.x;
    int nwarp = blockDim.x >> 5;

    float s = 0.f;
    for (int c = tid; c < NC; c += blockDim.x) s += xr[c];
    #pragma unroll
    for (int o = 16; o; o >>= 1) s += __shfl_xor_sync(0xffffffffu, s, o);
    if ((tid & 31) == 0) red[tid >> 5] = s;
    __syncthreads();
    if (tid < 32) {
        float v = (tid < nwarp) ? red[tid] : 0.f;
        #pragma unroll
        for (int o = 16; o; o >>= 1) v += __shfl_xor_sync(0xffffffffu, v, o);
        if (tid == 0) red[0] = v;
    }
    __syncthreads();
    float mu = red[0] * (1.0f / NC);
    __syncthreads();

    float s2 = 0.f;
    for (int c = tid; c < NC; c += blockDim.x) {
        float d = xr[c] - mu;
        s2 += d * d;
    }
    #pragma unroll
    for (int o = 16; o; o >>= 1) s2 += __shfl_xor_sync(0xffffffffu, s2, o);
    if ((tid & 31) == 0) red[tid >> 5] = s2;
    __syncthreads();
    if (tid < 32) {
        float v = (tid < nwarp) ? red[tid] : 0.f;
        #pragma unroll
        for (int o = 16; o; o >>= 1) v += __shfl_xor_sync(0xffffffffu, v, o);
        if (tid == 0) red[0] = v;
    }
    __syncthreads();
    float var = red[0] * (1.0f / NC);
    float rstd = rsqrtf(var + 1e-5f);
    float* outr = out + (size_t)row * NC;
    for (int c = tid; c < NC; c += blockDim.x)
        outr[c] = (xr[c] - mu) * rstd * w[c] + b[c];
}

// =====================================================================
// Tensor-core GEMM: tf32 3x-split mma.sync, block 128x64x32, 8 warps
// =====================================================================
#define TBM 128
#define TBN 64
#define TBK 32

__device__ __forceinline__ float gelu_f(float u) {
    return 0.5f * u * (1.0f + tanhf(0.7978845608028654f * (u + 0.044715f * u * u * u)));
}

__device__ __forceinline__ void split_tf32(float x, unsigned& hi, unsigned& lo) {
    unsigned h;
    asm("cvt.rna.tf32.f32 %0, %1;" : "=r"(h) : "f"(x));
    float l = x - __uint_as_float(h);
    asm("cvt.rna.tf32.f32 %0, %1;" : "=r"(lo) : "f"(l));
    hi = h;
}

__device__ __forceinline__ void mma_tf32(float* c,
                                         unsigned a0, unsigned a1, unsigned a2, unsigned a3,
                                         unsigned b0, unsigned b1) {
    asm volatile(
        "mma.sync.aligned.m16n8k8.row.col.f32.tf32.tf32.f32 "
        "{%0,%1,%2,%3}, {%4,%5,%6,%7}, {%8,%9}, {%0,%1,%2,%3};"
        : "+f"(c[0]), "+f"(c[1]), "+f"(c[2]), "+f"(c[3])
        : "r"(a0), "r"(a1), "r"(a2), "r"(a3), "r"(b0), "r"(b1));
}

// NN: C[M,N] = A[M,K] @ W[K,N] (+bias)(gelu?)(+res). N % 64 == 0, K % 32 == 0, M % 128 == 0.
__global__ void __launch_bounds__(256) tc_gemm_nn(
    const float* __restrict__ A, const float* __restrict__ W,
    const float* __restrict__ bias, const float* __restrict__ res,
    float* __restrict__ C, int M, int N, int K, int act)
{
    __shared__ float As[TBM][TBK + 4];
    __shared__ float Bs[TBK][TBN + 8];

    int tid = threadIdx.x;
    int lane = tid & 31, warp = tid >> 5;
    int wm = (warp & 3) * 32;
    int wn = (warp >> 2) * 32;
    int g = lane >> 2, t4 = lane & 3;

    int bm = blockIdx.y * TBM;
    int bn = blockIdx.x * TBN;

    float c[2][4][4] = {};

    for (int k0 = 0; k0 < K; k0 += TBK) {
        #pragma unroll
        for (int i = 0; i < 4; i++) {
            int idx = tid + i * 256;
            int r = idx >> 3, c4 = (idx & 7) << 2;
            float4 v = *(const float4*)(A + (size_t)(bm + r) * K + k0 + c4);
            *(float4*)&As[r][c4] = v;
        }
        #pragma unroll
        for (int i = 0; i < 2; i++) {
            int idx = tid + i * 256;
            int r = idx >> 4, c4 = (idx & 15) << 2;
            float4 v = *(const float4*)(W + (size_t)(k0 + r) * N + bn + c4);
            *(float4*)&Bs[r][c4] = v;
        }
        __syncthreads();

        #pragma unroll
        for (int kk = 0; kk < TBK; kk += 8) {
            unsigned ah[2][4], al[2][4];
            #pragma unroll
            for (int im = 0; im < 2; im++) {
                int mo = wm + im * 16;
                split_tf32(As[mo + g][kk + t4],         ah[im][0], al[im][0]);
                split_tf32(As[mo + g + 8][kk + t4],     ah[im][1], al[im][1]);
                split_tf32(As[mo + g][kk + t4 + 4],     ah[im][2], al[im][2]);
                split_tf32(As[mo + g + 8][kk + t4 + 4], ah[im][3], al[im][3]);
            }
            #pragma unroll
            for (int jn = 0; jn < 4; jn++) {
                int no = wn + jn * 8 + g;
                unsigned bh0, bl0, bh1, bl1;
                split_tf32(Bs[kk + t4][no],     bh0, bl0);
                split_tf32(Bs[kk + t4 + 4][no], bh1, bl1);
                #pragma unroll
                for (int im = 0; im < 2; im++) {
                    mma_tf32(c[im][jn], ah[im][0], ah[im][1], ah[im][2], ah[im][3], bh0, bh1);
                    mma_tf32(c[im][jn], ah[im][0], ah[im][1], ah[im][2], ah[im][3], bl0, bl1);
                    mma_tf32(c[im][jn], al[im][0], al[im][1], al[im][2], al[im][3], bh0, bh1);
                }
            }
        }
        __syncthreads();
    }

    #pragma unroll
    for (int im = 0; im < 2; im++) {
        #pragma unroll
        for (int jn = 0; jn < 4; jn++) {
            int row0 = bm + wm + im * 16 + g;
            int col0 = bn + wn + jn * 8 + t4 * 2;
            #pragma unroll
            for (int p = 0; p < 4; p++) {
                int row = row0 + (p >> 1) * 8;
                int col = col0 + (p & 1);
                float v = c[im][jn][p];
                if (bias) v += bias[col];
                if (act) v = gelu_f(v);
                if (res) v += res[(size_t)row * N + col];
                C[(size_t)row * N + col] = v;
            }
        }
    }
}

// NT: C[M,N] = A[M,K] @ Bt[N,K]^T  (lm_head). Ragged N allowed. grid: (M/128, ceil(N/64))
__global__ void __launch_bounds__(256) tc_gemm_nt(
    const float* __restrict__ A, const float* __restrict__ Bt,
    float* __restrict__ C, int M, int N, int K)
{
    __shared__ float As[TBM][TBK + 4];
    __shared__ float Bs[TBK][TBN + 8];

    int tid = threadIdx.x;
    int lane = tid & 31, warp = tid >> 5;
    int wm = (warp & 3) * 32;
    int wn = (warp >> 2) * 32;
    int g = lane >> 2, t4 = lane & 3;

    int bm = blockIdx.x * TBM;   // m fastest -> B column tile shared in L2 across wave
    int bn = blockIdx.y * TBN;

    float c[2][4][4] = {};

    for (int k0 = 0; k0 < K; k0 += TBK) {
        #pragma unroll
        for (int i = 0; i < 4; i++) {
            int idx = tid + i * 256;
            int r = idx >> 3, c4 = (idx & 7) << 2;
            float4 v = *(const float4*)(A + (size_t)(bm + r) * K + k0 + c4);
            *(float4*)&As[r][c4] = v;
        }
        #pragma unroll
        for (int i = 0; i < 2; i++) {
            int idx = tid + i * 256;       // 0..511: n = idx%64, kq = (idx/64)*4
            int n = idx & 63;
            int kq = (idx >> 6) << 2;
            int gn = bn + n;
            float4 v = make_float4(0.f, 0.f, 0.f, 0.f);
            if (gn < N) v = *(const float4*)(Bt + (size_t)gn * K + k0 + kq);
            Bs[kq + 0][n] = v.x; Bs[kq + 1][n] = v.y;
            Bs[kq + 2][n] = v.z; Bs[kq + 3][n] = v.w;
        }
        __syncthreads();

        #pragma unroll
        for (int kk = 0; kk < TBK; kk += 8) {
            unsigned ah[2][4], al[2][4];
            #pragma unroll
            for (int im = 0; im < 2; im++) {
                int mo = wm + im * 16;
                split_tf32(As[mo + g][kk + t4],         ah[im][0], al[im][0]);
                split_tf32(As[mo + g + 8][kk + t4],     ah[im][1], al[im][1]);
                split_tf32(As[mo + g][kk + t4 + 4],     ah[im][2], al[im][2]);
                split_tf32(As[mo + g + 8][kk + t4 + 4], ah[im][3], al[im][3]);
            }
            #pragma unroll
            for (int jn = 0; jn < 4; jn++) {
                int no = wn + jn * 8 + g;
                unsigned bh0, bl0, bh1, bl1;
                split_tf32(Bs[kk + t4][no],     bh0, bl0);
                split_tf32(Bs[kk + t4 + 4][no], bh1, bl1);
                #pragma unroll
                for (int im = 0; im < 2; im++) {
                    mma_tf32(c[im][jn], ah[im][0], ah[im][1], ah[im][2], ah[im][3], bh0, bh1);
                    mma_tf32(c[im][jn], ah[im][0], ah[im][1], ah[im][2], ah[im][3], bl0, bl1);
                    mma_tf32(c[im][jn], al[im][0], al[im][1], al[im][2], al[im][3], bh0, bh1);
                }
            }
        }
        __syncthreads();
    }

    #pragma unroll
    for (int im = 0; im < 2; im++) {
        #pragma unroll
        for (int jn = 0; jn < 4; jn++) {
            int row0 = bm + wm + im * 16 + g;
            int col0 = bn + wn + jn * 8 + t4 * 2;
            #pragma unroll
            for (int p = 0; p < 4; p++) {
                int row = row0 + (p >> 1) * 8;
                int col = col0 + (p & 1);
                if (col < N)
                    C[(size_t)row * N + col] = c[im][jn][p];
            }
        }
    }
}

// =====================================================================
// Causal attention (unchanged; ~68us total)
// =====================================================================
__global__ void attn_kernel(const float* __restrict__ qkv, float* __restrict__ y) {
    int q = blockIdx.x;
    int h = blockIdx.y;
    int b = blockIdx.z;
    int tid = threadIdx.x;

    __shared__ float qs[ND];
    __shared__ float sc[NT];
    __shared__ float red[32];
    __shared__ float yp[2][ND];

    const size_t rs = 3 * NC;
    const float* qptr = qkv + ((size_t)(b * NT + q)) * rs + h * ND;
    if (tid < ND) qs[tid] = qptr[tid];
    __syncthreads();

    const float scale = 0.125f;
    int nk = q + 1;
    const float* kbase = qkv + ((size_t)b * NT) * rs + NC + h * ND;
    for (int k = tid; k < nk; k += blockDim.x) {
        const float* kp = kbase + (size_t)k * rs;
        float d = 0.f;
        #pragma unroll
        for (int i = 0; i < ND; i++) d = fmaf(qs[i], kp[i], d);
        sc[k] = d * scale;
    }
    __syncthreads();

    float m = -1e30f;
    for (int k = tid; k < nk; k += blockDim.x) m = fmaxf(m, sc[k]);
    #pragma unroll
    for (int o = 16; o; o >>= 1) m = fmaxf(m, __shfl_xor_sync(0xffffffffu, m, o));
    if ((tid & 31) == 0) red[tid >> 5] = m;
    __syncthreads();
    if (tid < 32) {
        float v = (tid < (int)(blockDim.x >> 5)) ? red[tid] : -1e30f;
        #pragma unroll
        for (int o = 16; o; o >>= 1) v = fmaxf(v, __shfl_xor_sync(0xffffffffu, v, o));
        if (tid == 0) red[0] = v;
    }
    __syncthreads();
    m = red[0];
    __syncthreads();

    float s = 0.f;
    for (int k = tid; k < nk; k += blockDim.x) {
        float e = __expf(sc[k] - m);
        sc[k] = e;
        s += e;
    }
    #pragma unroll
    for (int o = 16; o; o >>= 1) s += __shfl_xor_sync(0xffffffffu, s, o);
    if ((tid & 31) == 0) red[tid >> 5] = s;
    __syncthreads();
    if (tid < 32) {
        float v = (tid < (int)(blockDim.x >> 5)) ? red[tid] : 0.f;
        #pragma unroll
        for (int o = 16; o; o >>= 1) v += __shfl_xor_sync(0xffffffffu, v, o);
        if (tid == 0) red[0] = v;
    }
    __syncthreads();
    float inv = 1.0f / red[0];

    int part = tid >> 6, d = tid & 63;
    const float* vbase = qkv + ((size_t)b * NT) * rs + 2 * NC + h * ND;
    float acc = 0.f;
    for (int k = part; k < nk; k += 2)
        acc = fmaf(sc[k], vbase[(size_t)k * rs + d], acc);
    yp[part][d] = acc;
    __syncthreads();
    if (tid < ND)
        y[((size_t)(b * NT + q)) * NC + h * ND + tid] = (yp[0][tid] + yp[1][tid]) * inv;
}

// =====================================================================
// launch
// =====================================================================
extern "C" void kernel_launch(void* const* d_in, const int* in_sizes, int n_in,
                              void* d_out, int out_size) {
    const int*   idx    = (const int*)d_in[0];
    const float* wte    = (const float*)d_in[1];
    const float* wpe    = (const float*)d_in[2];
    const float* ln1_w  = (const float*)d_in[3];
    const float* ln1_b  = (const float*)d_in[4];
    const float* ln2_w  = (const float*)d_in[5];
    const float* ln2_b  = (const float*)d_in[6];
    const float* attn_w = (const float*)d_in[7];
    const float* attn_b = (const float*)d_in[8];
    const float* proj_w = (const float*)d_in[9];
    const float* proj_b = (const float*)d_in[10];
    const float* fc_w   = (const float*)d_in[11];
    const float* fc_b   = (const float*)d_in[12];
    const float* fcp_w  = (const float*)d_in[13];
    const float* fcp_b  = (const float*)d_in[14];
    const float* lnf_w  = (const float*)d_in[15];
    const float* lnf_b  = (const float*)d_in[16];
    const float* lmh    = (const float*)d_in[17];
    float* out = (float*)d_out;

    float *x, *h, *qkv, *y, *fc;
    cudaGetSymbolAddress((void**)&x, g_x);
    cudaGetSymbolAddress((void**)&h, g_h);
    cudaGetSymbolAddress((void**)&qkv, g_qkv);
    cudaGetSymbolAddress((void**)&y, g_y);
    cudaGetSymbolAddress((void**)&fc, g_fc);

    embed_kernel<<<NTOK, 256>>>(idx, wte, wpe, x);

    for (int l = 0; l < NL; l++) {
        ln_kernel<<<NTOK, 256>>>(x, ln1_w + l * NC, ln1_b + l * NC, h);
        {
            dim3 grid((3 * NC) / TBN, NTOK / TBM);
            tc_gemm_nn<<<grid, 256>>>(h, attn_w + (size_t)l * NC * 3 * NC,
                                      attn_b + (size_t)l * 3 * NC, nullptr,
                                      qkv, NTOK, 3 * NC, NC, 0);
        }
        {
            dim3 grid(NT, NH, NB);
            attn_kernel<<<grid, 128>>>(qkv, y);
        }
        {
            dim3 grid(NC / TBN, NTOK / TBM);
            tc_gemm_nn<<<grid, 256>>>(y, proj_w + (size_t)l * NC * NC,
                                      proj_b + (size_t)l * NC, x,
                                      x, NTOK, NC, NC, 0);
        }
        ln_kernel<<<NTOK, 256>>>(x, ln2_w + l * NC, ln2_b + l * NC, h);
        {
            dim3 grid((4 * NC) / TBN, NTOK / TBM);
            tc_gemm_nn<<<grid, 256>>>(h, fc_w + (size_t)l * NC * 4 * NC,
                                      fc_b + (size_t)l * 4 * NC, nullptr,
                                      fc, NTOK, 4 * NC, NC, 1);
        }
        {
            dim3 grid(NC / TBN, NTOK / TBM);
            tc_gemm_nn<<<grid, 256>>>(fc, fcp_w + (size_t)l * 4 * NC * NC,
                                      fcp_b + (size_t)l * NC, x,
                                      x, NTOK, NC, 4 * NC, 0);
        }
    }

    ln_kernel<<<NTOK, 256>>>(x, lnf_w, lnf_b, h);

    {
        dim3 grid(NTOK / TBM, (NV + TBN - 1) / TBN);
        tc_gemm_nt<<<grid, 256>>>(h, lmh, out, NTOK, NV, NC);
    }
}

// round 4
// speedup vs baseline: 1.2217x; 1.0810x over previous
#include <cuda_runtime.h>
#include <cuda_fp16.h>
#include <math.h>

// ---- problem constants ----
#define NL 12
#define NH 12
#define NC 768
#define NV 50257
#define NT 1024
#define NB 4
#define ND 64
#define NTOK (NB * NT)   // 4096

// ---- fp32 activation scratch ----
__device__ float g_x[NTOK * NC];
__device__ float g_h[NTOK * NC];
__device__ float g_qkv[NTOK * 3 * NC];
__device__ float g_y[NTOK * NC];
__device__ float g_fc[NTOK * 4 * NC];

// ---- pre-split fp16 weight scratch (hi/lo planes, [N][K] layout) ----
__device__ __half g_wa_h[12 * 2304 * 768], g_wa_l[12 * 2304 * 768];
__device__ __half g_wp_h[12 * 768 * 768],  g_wp_l[12 * 768 * 768];
__device__ __half g_wf_h[12 * 3072 * 768], g_wf_l[12 * 3072 * 768];
__device__ __half g_wq_h[12 * 768 * 3072], g_wq_l[12 * 768 * 3072];
__device__ __half g_lm_h[50257 * 768],     g_lm_l[50257 * 768];

// =====================================================================
// Weight conversion: transpose [K][N] fp32 -> [N][K] fp16 hi/lo
// =====================================================================
__global__ void transpose_split(const float* __restrict__ W,
                                __half* __restrict__ OH, __half* __restrict__ OL,
                                int K, int N) {
    __shared__ float t[32][33];
    int l = blockIdx.z;
    const float* Wl = W + (size_t)l * K * N;
    __half* OHl = OH + (size_t)l * K * N;
    __half* OLl = OL + (size_t)l * K * N;
    int n0 = blockIdx.x * 32, k0 = blockIdx.y * 32;
    int tx = threadIdx.x, ty = threadIdx.y;
    #pragma unroll
    for (int i = ty; i < 32; i += 8)
        t[i][tx] = Wl[(size_t)(k0 + i) * N + n0 + tx];
    __syncthreads();
    #pragma unroll
    for (int i = ty; i < 32; i += 8) {
        float v = t[tx][i];
        __half h = __float2half_rn(v);
        OHl[(size_t)(n0 + i) * K + k0 + tx] = h;
        OLl[(size_t)(n0 + i) * K + k0 + tx] = __float2half_rn(v - __half2float(h));
    }
}

// lm_head is already [N][K]: elementwise split only
__global__ void split_kernel(const float* __restrict__ W,
                             __half* __restrict__ H, __half* __restrict__ L,
                             int n) {
    int i = blockIdx.x * blockDim.x + threadIdx.x;
    if (i < n) {
        float x = W[i];
        __half h = __float2half_rn(x);
        H[i] = h;
        L[i] = __float2half_rn(x - __half2float(h));
    }
}

// =====================================================================
// Embedding
// =====================================================================
__global__ void embed_kernel(const int* __restrict__ idx,
                             const float* __restrict__ wte,
                             const float* __restrict__ wpe,
                             float* __restrict__ x) {
    int row = blockIdx.x;
    int t = row % NT;
    int tok = idx[row];
    const float* we = wte + (size_t)tok * NC;
    const float* wp = wpe + (size_t)t * NC;
    float* out = x + (size_t)row * NC;
    for (int c = threadIdx.x; c < NC; c += blockDim.x)
        out[c] = we[c] + wp[c];
}

// =====================================================================
// LayerNorm
// =====================================================================
__global__ void ln_kernel(const float* __restrict__ x,
                          const float* __restrict__ w,
                          const float* __restrict__ b,
                          float* __restrict__ out) {
    int row = blockIdx.x;
    const float* xr = x + (size_t)row * NC;
    __shared__ float red[32];
    int tid = threadIdx.x;
    int nwarp = blockDim.x >> 5;

    float s = 0.f;
    for (int c = tid; c < NC; c += blockDim.x) s += xr[c];
    #pragma unroll
    for (int o = 16; o; o >>= 1) s += __shfl_xor_sync(0xffffffffu, s, o);
    if ((tid & 31) == 0) red[tid >> 5] = s;
    __syncthreads();
    if (tid < 32) {
        float v = (tid < nwarp) ? red[tid] : 0.f;
        #pragma unroll
        for (int o = 16; o; o >>= 1) v += __shfl_xor_sync(0xffffffffu, v, o);
        if (tid == 0) red[0] = v;
    }
    __syncthreads();
    float mu = red[0] * (1.0f / NC);
    __syncthreads();

    float s2 = 0.f;
    for (int c = tid; c < NC; c += blockDim.x) {
        float d = xr[c] - mu;
        s2 += d * d;
    }
    #pragma unroll
    for (int o = 16; o; o >>= 1) s2 += __shfl_xor_sync(0xffffffffu, s2, o);
    if ((tid & 31) == 0) red[tid >> 5] = s2;
    __syncthreads();
    if (tid < 32) {
        float v = (tid < nwarp) ? red[tid] : 0.f;
        #pragma unroll
        for (int o = 16; o; o >>= 1) v += __shfl_xor_sync(0xffffffffu, v, o);
        if (tid == 0) red[0] = v;
    }
    __syncthreads();
    float var = red[0] * (1.0f / NC);
    float rstd = rsqrtf(var + 1e-5f);
    float* outr = out + (size_t)row * NC;
    for (int c = tid; c < NC; c += blockDim.x)
        outr[c] = (xr[c] - mu) * rstd * w[c] + b[c];
}

// =====================================================================
// fp16 split-GEMM (NT): C[M,N] = A[M,K] @ B[N,K]^T  (+bias)(gelu?)(+res)
// A fp32 (split on the fly), B pre-split fp16 hi/lo.
// block 128x128x32, 8 warps (warp tile 64x32), double-buffered smem.
// =====================================================================
#define HBM 128
#define HBN 128
#define HBK 32
#define RS 20                 // row stride in uint32 (16 data + 4 pad)
#define PL (128 * RS)         // plane size in uint32 = 2560
#define HSMEM_BYTES (2 * 4 * PL * 4)   // 81920

__device__ __forceinline__ float gelu_f(float u) {
    return 0.5f * u * (1.0f + tanhf(0.7978845608028654f * (u + 0.044715f * u * u * u)));
}

__device__ __forceinline__ void mma_f16(float* c, const unsigned* a,
                                        unsigned b0, unsigned b1) {
    asm volatile(
        "mma.sync.aligned.m16n8k16.row.col.f32.f16.f16.f32 "
        "{%0,%1,%2,%3}, {%4,%5,%6,%7}, {%8,%9}, {%0,%1,%2,%3};"
        : "+f"(c[0]), "+f"(c[1]), "+f"(c[2]), "+f"(c[3])
        : "r"(a[0]), "r"(a[1]), "r"(a[2]), "r"(a[3]), "r"(b0), "r"(b1));
}

__device__ __forceinline__ unsigned pack_h2(__half a, __half b) {
    __half2 h = __halves2half2(a, b);
    return *reinterpret_cast<unsigned*>(&h);
}

__device__ __forceinline__ void ldg_A(const float* A, int bm, int K, int kbase,
                                      int ar, int ak, float4* r) {
    #pragma unroll
    for (int i = 0; i < 4; i++)
        r[i] = *(const float4*)(A + (size_t)(bm + ar) * K + kbase + ak + 4 * i);
}

__device__ __forceinline__ void sts_A(unsigned* AsH, unsigned* AsL,
                                      int ar, int ak, const float4* r) {
    #pragma unroll
    for (int i = 0; i < 4; i++) {
        float4 v = r[i];
        int cu = (ak + 4 * i) >> 1;
        __half hx = __float2half_rn(v.x), hy = __float2half_rn(v.y);
        __half hz = __float2half_rn(v.z), hw = __float2half_rn(v.w);
        float lx = v.x - __half2float(hx), ly = v.y - __half2float(hy);
        float lz = v.z - __half2float(hz), lw = v.w - __half2float(hw);
        AsH[ar * RS + cu]     = pack_h2(hx, hy);
        AsH[ar * RS + cu + 1] = pack_h2(hz, hw);
        AsL[ar * RS + cu]     = pack_h2(__float2half_rn(lx), __float2half_rn(ly));
        AsL[ar * RS + cu + 1] = pack_h2(__float2half_rn(lz), __float2half_rn(lw));
    }
}

__device__ __forceinline__ void load_B(const __half* Bh, const __half* Bl,
                                       unsigned* BsH, unsigned* BsL,
                                       int bn, int N, int K, int kbase, int tid) {
    #pragma unroll
    for (int i = 0; i < 4; i++) {
        int o = i * 256 + tid;
        int p = o >> 9;
        int oo = o & 511;
        int br = oo >> 2, seg = oo & 3;
        unsigned* dst = (p ? BsL : BsH) + br * RS + seg * 4;
        int gn = bn + br;
        if (gn < N) {
            const __half* src = (p ? Bl : Bh) + (size_t)gn * K + kbase + seg * 8;
            unsigned da = (unsigned)__cvta_generic_to_shared(dst);
            asm volatile("cp.async.cg.shared.global [%0], [%1], 16;"
                         :: "r"(da), "l"(src));
        } else {
            *reinterpret_cast<uint4*>(dst) = make_uint4(0, 0, 0, 0);
        }
    }
}

__global__ void __launch_bounds__(256) hgemm_nt(
    const float* __restrict__ A,
    const __half* __restrict__ Bh, const __half* __restrict__ Bl,
    const float* __restrict__ bias, const float* __restrict__ res,
    float* __restrict__ C, int M, int N, int K, int act, int swap)
{
    extern __shared__ unsigned sm[];

    int tid = threadIdx.x;
    int lane = tid & 31, warp = tid >> 5;
    int g = lane >> 2, t4 = lane & 3;
    int wm = (warp >> 2) * 64;   // 0 / 64
    int wn = (warp & 3) * 32;    // 0..96

    int bm = (swap ? blockIdx.x : blockIdx.y) * HBM;
    int bn = (swap ? blockIdx.y : blockIdx.x) * HBN;

    int ar = tid >> 1;
    int ak = (tid & 1) * 16;

    float c[4][4][4] = {};
    float4 areg[4];

    const int S = K / HBK;

    // prologue: stage 0 into buffer 0
    ldg_A(A, bm, K, 0, ar, ak, areg);
    load_B(Bh, Bl, sm + 2 * PL, sm + 3 * PL, bn, N, K, 0, tid);
    asm volatile("cp.async.commit_group;");
    sts_A(sm, sm + PL, ar, ak, areg);
    asm volatile("cp.async.wait_group 0;");
    __syncthreads();

    for (int s = 0; s < S; s++) {
        int cur = s & 1, nxt = cur ^ 1;
        unsigned* base = sm + cur * 4 * PL;
        const unsigned* Ah = base;
        const unsigned* Al = base + PL;
        const unsigned* Bhs = base + 2 * PL;
        const unsigned* Bls = base + 3 * PL;
        unsigned* nbase = sm + nxt * 4 * PL;

        bool more = (s + 1 < S);
        if (more) {
            ldg_A(A, bm, K, (s + 1) * HBK, ar, ak, areg);
            load_B(Bh, Bl, nbase + 2 * PL, nbase + 3 * PL, bn, N, K, (s + 1) * HBK, tid);
            asm volatile("cp.async.commit_group;");
        }

        #pragma unroll
        for (int kk = 0; kk < 2; kk++) {
            int kd = kk * 8;
            unsigned ah[4][4], al[4][4];
            #pragma unroll
            for (int im = 0; im < 4; im++) {
                int r = (wm + im * 16 + g) * RS;
                int r8 = r + 8 * RS;
                ah[im][0] = Ah[r + kd + t4];
                ah[im][1] = Ah[r8 + kd + t4];
                ah[im][2] = Ah[r + kd + 4 + t4];
                ah[im][3] = Ah[r8 + kd + 4 + t4];
                al[im][0] = Al[r + kd + t4];
                al[im][1] = Al[r8 + kd + t4];
                al[im][2] = Al[r + kd + 4 + t4];
                al[im][3] = Al[r8 + kd + 4 + t4];
            }
            #pragma unroll
            for (int jn = 0; jn < 4; jn++) {
                int n = (wn + jn * 8 + g) * RS;
                unsigned bh0 = Bhs[n + kd + t4], bh1 = Bhs[n + kd + 4 + t4];
                unsigned bl0 = Bls[n + kd + t4], bl1 = Bls[n + kd + 4 + t4];
                #pragma unroll
                for (int im = 0; im < 4; im++) {
                    mma_f16(c[im][jn], ah[im], bh0, bh1);
                    mma_f16(c[im][jn], ah[im], bl0, bl1);
                    mma_f16(c[im][jn], al[im], bh0, bh1);
                }
            }
        }

        if (more)
            sts_A(nbase, nbase + PL, ar, ak, areg);
        asm volatile("cp.async.wait_group 0;");
        __syncthreads();
    }

    // epilogue
    #pragma unroll
    for (int im = 0; im < 4; im++) {
        #pragma unroll
        for (int jn = 0; jn < 4; jn++) {
            int row0 = bm + wm + im * 16 + g;
            int col0 = bn + wn + jn * 8 + t4 * 2;
            #pragma unroll
            for (int p = 0; p < 4; p++) {
                int row = row0 + (p >> 1) * 8;
                int col = col0 + (p & 1);
                if (col < N) {
                    float v = c[im][jn][p];
                    if (bias) v += bias[col];
                    if (act) v = gelu_f(v);
                    if (res) v += res[(size_t)row * N + col];
                    C[(size_t)row * N + col] = v;
                }
            }
        }
    }
}

// =====================================================================
// Causal attention (unchanged)
// =====================================================================
__global__ void attn_kernel(const float* __restrict__ qkv, float* __restrict__ y) {
    int q = blockIdx.x;
    int h = blockIdx.y;
    int b = blockIdx.z;
    int tid = threadIdx.x;

    __shared__ float qs[ND];
    __shared__ float sc[NT];
    __shared__ float red[32];
    __shared__ float yp[2][ND];

    const size_t rs = 3 * NC;
    const float* qptr = qkv + ((size_t)(b * NT + q)) * rs + h * ND;
    if (tid < ND) qs[tid] = qptr[tid];
    __syncthreads();

    const float scale = 0.125f;
    int nk = q + 1;
    const float* kbase = qkv + ((size_t)b * NT) * rs + NC + h * ND;
    for (int k = tid; k < nk; k += blockDim.x) {
        const float* kp = kbase + (size_t)k * rs;
        float d = 0.f;
        #pragma unroll
        for (int i = 0; i < ND; i++) d = fmaf(qs[i], kp[i], d);
        sc[k] = d * scale;
    }
    __syncthreads();

    float m = -1e30f;
    for (int k = tid; k < nk; k += blockDim.x) m = fmaxf(m, sc[k]);
    #pragma unroll
    for (int o = 16; o; o >>= 1) m = fmaxf(m, __shfl_xor_sync(0xffffffffu, m, o));
    if ((tid & 31) == 0) red[tid >> 5] = m;
    __syncthreads();
    if (tid < 32) {
        float v = (tid < (int)(blockDim.x >> 5)) ? red[tid] : -1e30f;
        #pragma unroll
        for (int o = 16; o; o >>= 1) v = fmaxf(v, __shfl_xor_sync(0xffffffffu, v, o));
        if (tid == 0) red[0] = v;
    }
    __syncthreads();
    m = red[0];
    __syncthreads();

    float s = 0.f;
    for (int k = tid; k < nk; k += blockDim.x) {
        float e = __expf(sc[k] - m);
        sc[k] = e;
        s += e;
    }
    #pragma unroll
    for (int o = 16; o; o >>= 1) s += __shfl_xor_sync(0xffffffffu, s, o);
    if ((tid & 31) == 0) red[tid >> 5] = s;
    __syncthreads();
    if (tid < 32) {
        float v = (tid < (int)(blockDim.x >> 5)) ? red[tid] : 0.f;
        #pragma unroll
        for (int o = 16; o; o >>= 1) v += __shfl_xor_sync(0xffffffffu, v, o);
        if (tid == 0) red[0] = v;
    }
    __syncthreads();
    float inv = 1.0f / red[0];

    int part = tid >> 6, d = tid & 63;
    const float* vbase = qkv + ((size_t)b * NT) * rs + 2 * NC + h * ND;
    float acc = 0.f;
    for (int k = part; k < nk; k += 2)
        acc = fmaf(sc[k], vbase[(size_t)k * rs + d], acc);
    yp[part][d] = acc;
    __syncthreads();
    if (tid < ND)
        y[((size_t)(b * NT + q)) * NC + h * ND + tid] = (yp[0][tid] + yp[1][tid]) * inv;
}

// =====================================================================
// launch
// =====================================================================
extern "C" void kernel_launch(void* const* d_in, const int* in_sizes, int n_in,
                              void* d_out, int out_size) {
    const int*   idx    = (const int*)d_in[0];
    const float* wte    = (const float*)d_in[1];
    const float* wpe    = (const float*)d_in[2];
    const float* ln1_w  = (const float*)d_in[3];
    const float* ln1_b  = (const float*)d_in[4];
    const float* ln2_w  = (const float*)d_in[5];
    const float* ln2_b  = (const float*)d_in[6];
    const float* attn_w = (const float*)d_in[7];
    const float* attn_b = (const float*)d_in[8];
    const float* proj_w = (const float*)d_in[9];
    const float* proj_b = (const float*)d_in[10];
    const float* fc_w   = (const float*)d_in[11];
    const float* fc_b   = (const float*)d_in[12];
    const float* fcp_w  = (const float*)d_in[13];
    const float* fcp_b  = (const float*)d_in[14];
    const float* lnf_w  = (const float*)d_in[15];
    const float* lnf_b  = (const float*)d_in[16];
    const float* lmh    = (const float*)d_in[17];
    float* out = (float*)d_out;

    float *x, *h, *qkv, *y, *fc;
    cudaGetSymbolAddress((void**)&x, g_x);
    cudaGetSymbolAddress((void**)&h, g_h);
    cudaGetSymbolAddress((void**)&qkv, g_qkv);
    cudaGetSymbolAddress((void**)&y, g_y);
    cudaGetSymbolAddress((void**)&fc, g_fc);

    __half *wa_h, *wa_l, *wp_h, *wp_l, *wf_h, *wf_l, *wq_h, *wq_l, *lm_h, *lm_l;
    cudaGetSymbolAddress((void**)&wa_h, g_wa_h);
    cudaGetSymbolAddress((void**)&wa_l, g_wa_l);
    cudaGetSymbolAddress((void**)&wp_h, g_wp_h);
    cudaGetSymbolAddress((void**)&wp_l, g_wp_l);
    cudaGetSymbolAddress((void**)&wf_h, g_wf_h);
    cudaGetSymbolAddress((void**)&wf_l, g_wf_l);
    cudaGetSymbolAddress((void**)&wq_h, g_wq_h);
    cudaGetSymbolAddress((void**)&wq_l, g_wq_l);
    cudaGetSymbolAddress((void**)&lm_h, g_lm_h);
    cudaGetSymbolAddress((void**)&lm_l, g_lm_l);

    cudaFuncSetAttribute(hgemm_nt, cudaFuncAttributeMaxDynamicSharedMemorySize,
                         HSMEM_BYTES);

    // ---- weight conversion (every launch; ~0.2 ms) ----
    dim3 tb(32, 8);
    transpose_split<<<dim3(2304 / 32, 768 / 32, 12), tb>>>(attn_w, wa_h, wa_l, NC, 3 * NC);
    transpose_split<<<dim3(768 / 32, 768 / 32, 12), tb>>>(proj_w, wp_h, wp_l, NC, NC);
    transpose_split<<<dim3(3072 / 32, 768 / 32, 12), tb>>>(fc_w, wf_h, wf_l, NC, 4 * NC);
    transpose_split<<<dim3(768 / 32, 3072 / 32, 12), tb>>>(fcp_w, wq_h, wq_l, 4 * NC, NC);
    split_kernel<<<(NV * NC + 255) / 256, 256>>>(lmh, lm_h, lm_l, NV * NC);

    embed_kernel<<<NTOK, 256>>>(idx, wte, wpe, x);

    for (int l = 0; l < NL; l++) {
        ln_kernel<<<NTOK, 256>>>(x, ln1_w + l * NC, ln1_b + l * NC, h);
        {   // qkv = h @ attn_w + attn_b
            dim3 grid((3 * NC) / HBN, NTOK / HBM);
            hgemm_nt<<<grid, 256, HSMEM_BYTES>>>(
                h, wa_h + (size_t)l * 3 * NC * NC, wa_l + (size_t)l * 3 * NC * NC,
                attn_b + (size_t)l * 3 * NC, nullptr, qkv, NTOK, 3 * NC, NC, 0, 0);
        }
        {
            dim3 grid(NT, NH, NB);
            attn_kernel<<<grid, 128>>>(qkv, y);
        }
        {   // x = x + y @ proj_w + proj_b
            dim3 grid(NC / HBN, NTOK / HBM);
            hgemm_nt<<<grid, 256, HSMEM_BYTES>>>(
                y, wp_h + (size_t)l * NC * NC, wp_l + (size_t)l * NC * NC,
                proj_b + (size_t)l * NC, x, x, NTOK, NC, NC, 0, 0);
        }
        ln_kernel<<<NTOK, 256>>>(x, ln2_w + l * NC, ln2_b + l * NC, h);
        {   // fc = gelu(h @ fc_w + fc_b)
            dim3 grid((4 * NC) / HBN, NTOK / HBM);
            hgemm_nt<<<grid, 256, HSMEM_BYTES>>>(
                h, wf_h + (size_t)l * 4 * NC * NC, wf_l + (size_t)l * 4 * NC * NC,
                fc_b + (size_t)l * 4 * NC, nullptr, fc, NTOK, 4 * NC, NC, 1, 0);
        }
        {   // x = x + fc @ fcp_w + fcp_b
            dim3 grid(NC / HBN, NTOK / HBM);
            hgemm_nt<<<grid, 256, HSMEM_BYTES>>>(
                fc, wq_h + (size_t)l * 4 * NC * NC, wq_l + (size_t)l * 4 * NC * NC,
                fcp_b + (size_t)l * NC, x, x, NTOK, NC, 4 * NC, 0, 0);
        }
    }

    ln_kernel<<<NTOK, 256>>>(x, lnf_w, lnf_b, h);

    {   // logits = h @ lm_head^T  (m-fastest grid for B-tile L2 reuse)
        dim3 grid(NTOK / HBM, (NV + HBN - 1) / HBN);
        hgemm_nt<<<grid, 256, HSMEM_BYTES>>>(
            h, lm_h, lm_l, nullptr, nullptr, out, NTOK, NV, NC, 0, 1);
    }
}